// round 7
// baseline (speedup 1.0000x reference)
#include <cuda_runtime.h>
#include <cuda_bf16.h>
#include <cstdint>

// Problem constants
#define Bdim 8
#define Nseq 4096
#define Cdim 768
#define Hh   12
#define Dd   64
#define Mrows (Bdim * Nseq)      // 32768
#define ThreeC (3 * Cdim)        // 2304
#define BH (Bdim * Hh)           // 96
#define NSPLIT 4
#define KSPLIT 2304              // K' = 3*768 (hi/hi/lo folded split)

// GEMM tiling
#define BM 128
#define BN 256
#define BKK 32
#define KT2 (KSPLIT / BKK)       // 72
#define ROWB 80                  // smem row stride bytes (64B data + 16B pad)
#define ATILE (BM * ROWB)        // 10240
#define BTILE (BN * ROWB)        // 20480
#define STG (ATILE + BTILE)      // 30720
#define NSTAGE 6
#define GEMM_SMEM (NSTAGE * STG) // 184320

// ---------------------------------------------------------------------------
// Scratch (device globals -- no allocation allowed)
// ---------------------------------------------------------------------------
__device__ float          g_qkv[(size_t)Mrows * ThreeC];   // 302 MB fp32
__device__ __nv_bfloat16  g_xhi[(size_t)Mrows * Cdim];
__device__ __nv_bfloat16  g_xlo[(size_t)Mrows * Cdim];
__device__ __nv_bfloat16  g_ahi[(size_t)Mrows * Cdim];
__device__ __nv_bfloat16  g_alo[(size_t)Mrows * Cdim];
__device__ __nv_bfloat16  g_bqkv[(size_t)ThreeC * KSPLIT]; // Bt [2304][2304]
__device__ __nv_bfloat16  g_bproj[(size_t)Cdim * KSPLIT];  // Bt [768][2304]
__device__ float g_psum[NSPLIT * BH * Dd];
__device__ float g_ctxp[NSPLIT * BH * Dd * Dd];
__device__ float g_ctx[BH * Dd * Dd];

// ---------------------------------------------------------------------------
// PTX helpers (arch-portable: cp.async + ldmatrix + mma.sync only)
// ---------------------------------------------------------------------------
__device__ __forceinline__ uint32_t smem_u32_of(const void* p) {
    uint32_t a;
    asm("{ .reg .u64 t; cvta.to.shared.u64 t, %1; cvt.u32.u64 %0, t; }"
        : "=r"(a) : "l"(p));
    return a;
}

__device__ __forceinline__ void cp_async16(uint32_t dst, const void* src) {
    asm volatile("cp.async.cg.shared.global [%0], [%1], 16;\n"
                 :: "r"(dst), "l"(src) : "memory");
}
#define CP_COMMIT() asm volatile("cp.async.commit_group;" ::: "memory")
#define CP_WAIT2()  asm volatile("cp.async.wait_group 2;" ::: "memory")
#define CP_WAIT0()  asm volatile("cp.async.wait_group 0;" ::: "memory")

__device__ __forceinline__ void ldmatrix_x4(uint32_t* r, uint32_t addr) {
    asm volatile(
        "ldmatrix.sync.aligned.m8n8.x4.shared.b16 {%0,%1,%2,%3}, [%4];"
        : "=r"(r[0]), "=r"(r[1]), "=r"(r[2]), "=r"(r[3]) : "r"(addr));
}

__device__ __forceinline__ void mma16816(float* d, const uint32_t* a,
                                         const uint32_t* b) {
    asm volatile(
        "mma.sync.aligned.m16n8k16.row.col.f32.bf16.bf16.f32 "
        "{%0,%1,%2,%3}, {%4,%5,%6,%7}, {%8,%9}, {%0,%1,%2,%3};"
        : "+f"(d[0]), "+f"(d[1]), "+f"(d[2]), "+f"(d[3])
        : "r"(a[0]), "r"(a[1]), "r"(a[2]), "r"(a[3]), "r"(b[0]), "r"(b[1]));
}

// ---------------------------------------------------------------------------
// GEMM: C[M, Ntot] fp32 = split-bf16 A'' (M x 2304) @ B''t (Ntot x 2304)^T
// A'' K-chunks: kt in [0,24)x2 = hi cols, [48,72) = lo cols.
// Bt rows pre-built as [hi | lo | hi].
// BM=128, BN=256, BK=32, 512 threads (warp grid 4m x 4n),
// 6-stage cp.async pipeline, barrier every 2 kt, register-double-buffered
// ldmatrix fragments.
// ---------------------------------------------------------------------------
__device__ __forceinline__ void gemm_load_stage(
    const __nv_bfloat16* __restrict__ Ahi, const __nv_bfloat16* __restrict__ Alo,
    const __nv_bfloat16* __restrict__ Bt,
    size_t m0, size_t n0, int kt, int stage, uint32_t sb, int tid)
{
    int blk = kt / 24;
    const __nv_bfloat16* asrc = (blk < 2) ? Ahi : Alo;
    int acol = (kt - blk * 24) * BKK;
    int bcol = kt * BKK;
    uint32_t as = sb + stage * STG;
    uint32_t bs = as + ATILE;
    int lr = tid >> 2;          // 0..127
    int lc = tid & 3;           // 16B chunk within 64B row

    cp_async16(as + lr * ROWB + lc * 16,
               asrc + (m0 + lr) * Cdim + acol + lc * 8);
    cp_async16(bs + lr * ROWB + lc * 16,
               Bt + (n0 + lr) * (size_t)KSPLIT + bcol + lc * 8);
    cp_async16(bs + (lr + 128) * ROWB + lc * 16,
               Bt + (n0 + lr + 128) * (size_t)KSPLIT + bcol + lc * 8);
    CP_COMMIT();
}

__global__ __launch_bounds__(512, 1) void gemm_hmma_kernel(
    const __nv_bfloat16* __restrict__ Ahi,
    const __nv_bfloat16* __restrict__ Alo,
    const __nv_bfloat16* __restrict__ Bt,
    float* __restrict__ Cm, int ldc,
    const float* __restrict__ bias)
{
    extern __shared__ char smem[];
    uint32_t sb = smem_u32_of(smem);
    int tid = threadIdx.x;
    int lane = tid & 31, wid = tid >> 5;
    int wm = wid >> 2, wn = wid & 3;     // warp grid 4 (m) x 4 (n)

    size_t m0 = (size_t)blockIdx.y * BM;
    size_t n0 = (size_t)blockIdx.x * BN;

    // Per-thread ldmatrix byte offsets (within a stage)
    uint32_t a_off = (uint32_t)(wm * 32 + (lane & 15)) * ROWB + ((lane >> 4) << 4);
    uint32_t b_off = ATILE +
        (uint32_t)(wn * 64 + (lane & 7) + ((lane >> 4) << 3)) * ROWB +
        ((lane & 8) << 1);

    float acc[2][8][4];
    #pragma unroll
    for (int mf = 0; mf < 2; mf++)
        #pragma unroll
        for (int nf = 0; nf < 8; nf++)
            #pragma unroll
            for (int c = 0; c < 4; c++) acc[mf][nf][c] = 0.f;

    // Prologue: 4 stages in flight
    gemm_load_stage(Ahi, Alo, Bt, m0, n0, 0, 0, sb, tid);
    gemm_load_stage(Ahi, Alo, Bt, m0, n0, 1, 1, sb, tid);
    gemm_load_stage(Ahi, Alo, Bt, m0, n0, 2, 2, sb, tid);
    gemm_load_stage(Ahi, Alo, Bt, m0, n0, 3, 3, sb, tid);

    // Fragment double buffers
    uint32_t aF[2][2][4];
    uint32_t bF[2][4][4];

    for (int ktb = 0; ktb < KT2; ktb += 2) {
        // Stages ktb, ktb+1 must be resident.
        if (ktb + 3 < KT2) CP_WAIT2(); else CP_WAIT0();
        __syncthreads();
        // Refill two stages (slots last read at ktb-2 / ktb-1).
        if (ktb + 4 < KT2)
            gemm_load_stage(Ahi, Alo, Bt, m0, n0, ktb + 4, (ktb + 4) % NSTAGE, sb, tid);
        if (ktb + 5 < KT2)
            gemm_load_stage(Ahi, Alo, Bt, m0, n0, ktb + 5, (ktb + 5) % NSTAGE, sb, tid);

        uint32_t stg0 = sb + (ktb % NSTAGE) * STG;
        uint32_t stg1 = sb + ((ktb + 1) % NSTAGE) * STG;

        // Preload phase 0 (kt=ktb, ks=0) into buffer 0
        #pragma unroll
        for (int mf = 0; mf < 2; mf++)
            ldmatrix_x4(aF[0][mf], stg0 + a_off + mf * (16 * ROWB));
        #pragma unroll
        for (int nf2 = 0; nf2 < 4; nf2++)
            ldmatrix_x4(bF[0][nf2], stg0 + b_off + nf2 * (16 * ROWB));

        // 4 phases: (ktb,ks0) (ktb,ks1) (ktb+1,ks0) (ktb+1,ks1)
        #pragma unroll
        for (int p = 0; p < 4; p++) {
            int cur = p & 1;
            if (p < 3) {
                int nxt = (p + 1) & 1;
                uint32_t nstg = ((p + 1) >> 1) ? stg1 : stg0;
                uint32_t ko = ((p + 1) & 1) * 32;
                #pragma unroll
                for (int mf = 0; mf < 2; mf++)
                    ldmatrix_x4(aF[nxt][mf], nstg + a_off + mf * (16 * ROWB) + ko);
                #pragma unroll
                for (int nf2 = 0; nf2 < 4; nf2++)
                    ldmatrix_x4(bF[nxt][nf2], nstg + b_off + nf2 * (16 * ROWB) + ko);
            }
            #pragma unroll
            for (int mf = 0; mf < 2; mf++)
                #pragma unroll
                for (int nf = 0; nf < 8; nf++)
                    mma16816(acc[mf][nf], aF[cur][mf], &bF[cur][nf >> 1][(nf & 1) * 2]);
        }
    }

    // Epilogue: direct fp32 stores
    #pragma unroll
    for (int mf = 0; mf < 2; mf++) {
        size_t row = m0 + wm * 32 + mf * 16 + (lane >> 2);
        #pragma unroll
        for (int nf = 0; nf < 8; nf++) {
            int col = (int)n0 + wn * 64 + nf * 8 + (lane & 3) * 2;
            float b0 = 0.f, b1 = 0.f;
            if (bias) { b0 = bias[col]; b1 = bias[col + 1]; }
            float2 v0; v0.x = acc[mf][nf][0] + b0; v0.y = acc[mf][nf][1] + b1;
            float2 v1; v1.x = acc[mf][nf][2] + b0; v1.y = acc[mf][nf][3] + b1;
            *reinterpret_cast<float2*>(&Cm[row * (size_t)ldc + col]) = v0;
            *reinterpret_cast<float2*>(&Cm[(row + 8) * (size_t)ldc + col]) = v1;
        }
    }
}

// ---------------------------------------------------------------------------
// Split fp32 -> (hi, lo) bf16
// ---------------------------------------------------------------------------
__device__ __forceinline__ void split2(float v, __nv_bfloat16& h, __nv_bfloat16& l) {
    h = __float2bfloat16(v);
    l = __float2bfloat16(v - __bfloat162float(h));
}

__global__ __launch_bounds__(256) void split_kernel(
    const float* __restrict__ in, __nv_bfloat16* __restrict__ hi,
    __nv_bfloat16* __restrict__ lo, int n4)
{
    int i = blockIdx.x * 256 + threadIdx.x;
    if (i >= n4) return;
    float4 v = reinterpret_cast<const float4*>(in)[i];
    __nv_bfloat16 h0, h1, h2, h3, l0, l1, l2, l3;
    split2(v.x, h0, l0); split2(v.y, h1, l1);
    split2(v.z, h2, l2); split2(v.w, h3, l3);
    __nv_bfloat162* hp = reinterpret_cast<__nv_bfloat162*>(hi) + i * 2;
    __nv_bfloat162* lp = reinterpret_cast<__nv_bfloat162*>(lo) + i * 2;
    hp[0] = __nv_bfloat162(h0, h1); hp[1] = __nv_bfloat162(h2, h3);
    lp[0] = __nv_bfloat162(l0, l1); lp[1] = __nv_bfloat162(l2, l3);
}

// ---------------------------------------------------------------------------
// Build transposed split weight: W [768 x Nn] fp32 -> Bt [Nn x 2304] bf16
// rows of Bt: cols [0,768)=hi, [768,1536)=lo, [1536,2304)=hi
// ---------------------------------------------------------------------------
__global__ __launch_bounds__(256) void build_bt_kernel(
    const float* __restrict__ W, __nv_bfloat16* __restrict__ Bt, int Nn)
{
    __shared__ float t[32][33];
    int n0 = blockIdx.x * 32, k0 = blockIdx.y * 32;
    int tx = threadIdx.x, ty = threadIdx.y;   // (32, 8)
    #pragma unroll
    for (int j = 0; j < 32; j += 8)
        t[ty + j][tx] = W[(size_t)(k0 + ty + j) * Nn + n0 + tx];
    __syncthreads();
    #pragma unroll
    for (int j = 0; j < 32; j += 8) {
        int n = n0 + ty + j, k = k0 + tx;
        float v = t[tx][ty + j];
        __nv_bfloat16 h, l;
        split2(v, h, l);
        size_t base = (size_t)n * KSPLIT;
        Bt[base + k] = h;
        Bt[base + 768 + k] = l;
        Bt[base + 1536 + k] = h;
    }
}

// ---------------------------------------------------------------------------
// Partial context + partial exp-sums (no max subtraction: k ~ N(0,1), safe).
// ---------------------------------------------------------------------------
__global__ __launch_bounds__(256) void ctx_partial_kernel()
{
    int bh = blockIdx.x, split = blockIdx.y;
    int b = bh / Hh, h = bh - b * Hh;
    int n_start = split * (Nseq / NSPLIT);

    const float* kbase = g_qkv + (size_t)b * Nseq * ThreeC + Cdim + h * Dd;
    const float* vbase = g_qkv + (size_t)b * Nseq * ThreeC + 2 * Cdim + h * Dd;

    __shared__ float ks[16][68];
    __shared__ float vs[16][68];

    int tid = threadIdx.x;
    int lr = tid >> 4, lc = (tid & 15) * 4;
    int rowd = (tid >> 4) * 4, cole = (tid & 15) * 4;

    float acc[4][4];
    #pragma unroll
    for (int i = 0; i < 4; i++)
        #pragma unroll
        for (int j = 0; j < 4; j++) acc[i][j] = 0.f;
    float sum4[4] = {0.f, 0.f, 0.f, 0.f};

    for (int nt = 0; nt < Nseq / NSPLIT; nt += 16) {
        size_t off = (size_t)(n_start + nt + lr) * ThreeC + lc;
        float4 kv = *reinterpret_cast<const float4*>(&kbase[off]);
        float e0 = __expf(kv.x), e1 = __expf(kv.y);
        float e2 = __expf(kv.z), e3 = __expf(kv.w);
        ks[lr][lc + 0] = e0; ks[lr][lc + 1] = e1;
        ks[lr][lc + 2] = e2; ks[lr][lc + 3] = e3;
        sum4[0] += e0; sum4[1] += e1; sum4[2] += e2; sum4[3] += e3;
        *reinterpret_cast<float4*>(&vs[lr][lc]) =
            *reinterpret_cast<const float4*>(&vbase[off]);
        __syncthreads();

        #pragma unroll
        for (int kk = 0; kk < 16; kk++) {
            float4 a = *reinterpret_cast<const float4*>(&ks[kk][rowd]);
            float4 bb = *reinterpret_cast<const float4*>(&vs[kk][cole]);
            float af[4] = {a.x, a.y, a.z, a.w};
            float bv[4] = {bb.x, bb.y, bb.z, bb.w};
            #pragma unroll
            for (int i = 0; i < 4; i++)
                #pragma unroll
                for (int j = 0; j < 4; j++)
                    acc[i][j] += af[i] * bv[j];
        }
        __syncthreads();
    }

    float* outp = g_ctxp + (size_t)(split * BH + bh) * (Dd * Dd);
    #pragma unroll
    for (int i = 0; i < 4; i++) {
        float4 o;
        o.x = acc[i][0]; o.y = acc[i][1]; o.z = acc[i][2]; o.w = acc[i][3];
        *reinterpret_cast<float4*>(&outp[(rowd + i) * Dd + cole]) = o;
    }

    // Reduce per-column exp sums (16 row-groups) via smem
    ks[lr][lc + 0] = sum4[0]; ks[lr][lc + 1] = sum4[1];
    ks[lr][lc + 2] = sum4[2]; ks[lr][lc + 3] = sum4[3];
    __syncthreads();
    if (tid < 64) {
        float s = 0.f;
        #pragma unroll
        for (int r = 0; r < 16; r++) s += ks[r][tid];
        g_psum[(split * BH + bh) * Dd + tid] = s;
    }
}

__global__ __launch_bounds__(256) void ctx_reduce_kernel()
{
    int idx = blockIdx.x * 256 + threadIdx.x;
    const int total = BH * Dd * Dd;
    if (idx >= total) return;
    int bh = idx >> 12;
    int d = (idx & 4095) >> 6;
    float ksum = g_psum[(0 * BH + bh) * Dd + d]
               + g_psum[(1 * BH + bh) * Dd + d]
               + g_psum[(2 * BH + bh) * Dd + d]
               + g_psum[(3 * BH + bh) * Dd + d];
    float s = g_ctxp[idx] + g_ctxp[total + idx]
            + g_ctxp[2 * total + idx] + g_ctxp[3 * total + idx];
    g_ctx[idx] = s / ksum;
}

// ---------------------------------------------------------------------------
// attn = q @ ctx -> write bf16 hi/lo directly (A-side of GEMM2)
// ---------------------------------------------------------------------------
__global__ __launch_bounds__(256) void attn_out_kernel()
{
    int bh = blockIdx.x, nb = blockIdx.y;
    int b = bh / Hh, h = bh - b * Hh;
    int n0 = nb * 128;

    __shared__ float q_s[128][17];
    __shared__ float ctx_s[16][64];

    const float* qbase = g_qkv + (size_t)b * Nseq * ThreeC + h * Dd;
    const float* cbase = g_ctx + (size_t)bh * (Dd * Dd);

    int tid = threadIdx.x;
    int rowb = (tid >> 4) * 8;
    int col  = (tid & 15) * 4;

    float acc[8][4];
    #pragma unroll
    for (int i = 0; i < 8; i++)
        #pragma unroll
        for (int j = 0; j < 4; j++) acc[i][j] = 0.f;

    for (int dc = 0; dc < Dd; dc += 16) {
        #pragma unroll
        for (int t = 0; t < 2; t++) {
            int idx = tid + t * 256;
            int r = idx >> 2;
            int c4 = (idx & 3) * 4;
            float4 qv = *reinterpret_cast<const float4*>(
                &qbase[(size_t)(n0 + r) * ThreeC + dc + c4]);
            q_s[r][c4 + 0] = qv.x; q_s[r][c4 + 1] = qv.y;
            q_s[r][c4 + 2] = qv.z; q_s[r][c4 + 3] = qv.w;
        }
        {
            int r = tid >> 4;
            int c4 = (tid & 15) * 4;
            *reinterpret_cast<float4*>(&ctx_s[r][c4]) =
                *reinterpret_cast<const float4*>(&cbase[(size_t)(dc + r) * Dd + c4]);
        }
        __syncthreads();

        #pragma unroll
        for (int dd = 0; dd < 16; dd++) {
            float4 cf = *reinterpret_cast<const float4*>(&ctx_s[dd][col]);
            float cv[4] = {cf.x, cf.y, cf.z, cf.w};
            #pragma unroll
            for (int i = 0; i < 8; i++) {
                float qv = q_s[rowb + i][dd];
                #pragma unroll
                for (int j = 0; j < 4; j++) acc[i][j] += qv * cv[j];
            }
        }
        __syncthreads();
    }

    #pragma unroll
    for (int i = 0; i < 8; i++) {
        size_t base = ((size_t)b * Nseq + n0 + rowb + i) * Cdim + h * Dd + col;
        __nv_bfloat16 h0, h1, h2, h3, l0, l1, l2, l3;
        split2(acc[i][0], h0, l0); split2(acc[i][1], h1, l1);
        split2(acc[i][2], h2, l2); split2(acc[i][3], h3, l3);
        __nv_bfloat162* hp = reinterpret_cast<__nv_bfloat162*>(&g_ahi[base]);
        __nv_bfloat162* lp = reinterpret_cast<__nv_bfloat162*>(&g_alo[base]);
        hp[0] = __nv_bfloat162(h0, h1); hp[1] = __nv_bfloat162(h2, h3);
        lp[0] = __nv_bfloat162(l0, l1); lp[1] = __nv_bfloat162(l2, l3);
    }
}

// ---------------------------------------------------------------------------
extern "C" void kernel_launch(void* const* d_in, const int* in_sizes, int n_in,
                              void* d_out, int out_size)
{
    const float* x     = (const float*)d_in[0];   // [8,4096,768]
    const float* Wqkv  = (const float*)d_in[1];   // [768,2304]
    const float* Wproj = (const float*)d_in[2];   // [768,768]
    const float* bproj = (const float*)d_in[3];   // [768]
    float* out = (float*)d_out;

    float *qkv_ptr;
    __nv_bfloat16 *xhi, *xlo, *ahi, *alo, *bqkv, *bprojt;
    cudaGetSymbolAddress((void**)&qkv_ptr, g_qkv);
    cudaGetSymbolAddress((void**)&xhi, g_xhi);
    cudaGetSymbolAddress((void**)&xlo, g_xlo);
    cudaGetSymbolAddress((void**)&ahi, g_ahi);
    cudaGetSymbolAddress((void**)&alo, g_alo);
    cudaGetSymbolAddress((void**)&bqkv, g_bqkv);
    cudaGetSymbolAddress((void**)&bprojt, g_bproj);

    cudaFuncSetAttribute(gemm_hmma_kernel,
                         cudaFuncAttributeMaxDynamicSharedMemorySize, GEMM_SMEM);

    // 0) conversions
    split_kernel<<<(Mrows * Cdim / 4 + 255) / 256, 256>>>(x, xhi, xlo,
                                                          Mrows * Cdim / 4);
    build_bt_kernel<<<dim3(ThreeC / 32, Cdim / 32), dim3(32, 8)>>>(Wqkv, bqkv, ThreeC);
    build_bt_kernel<<<dim3(Cdim / 32, Cdim / 32), dim3(32, 8)>>>(Wproj, bprojt, Cdim);

    // 1) qkv = x @ Wqkv  (HMMA tensor cores, split bf16)
    gemm_hmma_kernel<<<dim3(ThreeC / BN, Mrows / BM), 512, GEMM_SMEM>>>(
        xhi, xlo, bqkv, qkv_ptr, ThreeC, nullptr);

    // 2-3) fused context + exp-sum partials, then reduce
    ctx_partial_kernel<<<dim3(BH, NSPLIT), 256>>>();
    ctx_reduce_kernel<<<(BH * Dd * Dd + 255) / 256, 256>>>();

    // 4) attn = q @ ctx -> bf16 hi/lo
    attn_out_kernel<<<dim3(BH, Nseq / 128), 256>>>();

    // 5) out = attn @ Wproj + bias  (HMMA tensor cores, split bf16)
    gemm_hmma_kernel<<<dim3(Cdim / BN, Mrows / BM), 512, GEMM_SMEM>>>(
        ahi, alo, bprojt, out, Cdim, bproj);
}